// round 2
// baseline (speedup 1.0000x reference)
#include <cuda_runtime.h>

#define WARPS_PER_BLOCK 8
#define THREADS (WARPS_PER_BLOCK * 32)

__global__ __launch_bounds__(THREADS)
void transh_score_kernel(
    const int* __restrict__ pos_h, const int* __restrict__ pos_t, const int* __restrict__ pos_r,
    const int* __restrict__ neg_h, const int* __restrict__ neg_t, const int* __restrict__ neg_r,
    const float4* __restrict__ ent,    // [ENT, 32] float4
    const float4* __restrict__ vvrel,  // [ENT, 32] float4
    const float4* __restrict__ bases,  // [REL, 32] float4
    float* __restrict__ out, int n)
{
    const int warp = (blockIdx.x * blockDim.x + threadIdx.x) >> 5;
    const int lane = threadIdx.x & 31;
    if (warp >= n) return;

    const int iph = __ldg(pos_h + warp);
    const int ipt = __ldg(pos_t + warp);
    const int ipr = __ldg(pos_r + warp);
    const int inh = __ldg(neg_h + warp);
    const int int_ = __ldg(neg_t + warp);
    const int inr = __ldg(neg_r + warp);

    // 128 floats per row = 32 float4; one float4 per lane.
    const float4 v  = __ldg(bases + (size_t)ipr * 32 + lane);
    const float4 h  = __ldg(ent   + (size_t)iph * 32 + lane);
    const float4 t  = __ldg(ent   + (size_t)ipt * 32 + lane);
    const float4 r  = __ldg(vvrel + (size_t)ipr * 32 + lane);
    const float4 nh = __ldg(ent   + (size_t)inh * 32 + lane);
    const float4 nt = __ldg(ent   + (size_t)int_ * 32 + lane);
    const float4 nr = __ldg(vvrel + (size_t)inr * 32 + lane);

    // Projection is linear and uses the same v for all six vectors:
    //   sum|P(h)+P(r)-P(t)| == sum|P(h+r-t)|
    float4 dp, dn;
    dp.x = h.x + r.x - t.x;  dp.y = h.y + r.y - t.y;
    dp.z = h.z + r.z - t.z;  dp.w = h.w + r.w - t.w;
    dn.x = nh.x + nr.x - nt.x;  dn.y = nh.y + nr.y - nt.y;
    dn.z = nh.z + nr.z - nt.z;  dn.w = nh.w + nr.w - nt.w;

    // Three dots in one butterfly reduction.
    float pvv = v.x * v.x + v.y * v.y + v.z * v.z + v.w * v.w;
    float pvp = v.x * dp.x + v.y * dp.y + v.z * dp.z + v.w * dp.w;
    float pvn = v.x * dn.x + v.y * dn.y + v.z * dn.z + v.w * dn.w;
    #pragma unroll
    for (int o = 16; o > 0; o >>= 1) {
        pvv += __shfl_xor_sync(0xFFFFFFFFu, pvv, o);
        pvp += __shfl_xor_sync(0xFFFFFFFFu, pvp, o);
        pvn += __shfl_xor_sync(0xFFFFFFFFu, pvn, o);
    }
    const float inv_vv = 1.0f / pvv;
    const float cp = pvp * inv_vv;
    const float cn = pvn * inv_vv;

    // L1 norm of projected differences, two sums in one butterfly.
    float sp = fabsf(dp.x - cp * v.x) + fabsf(dp.y - cp * v.y)
             + fabsf(dp.z - cp * v.z) + fabsf(dp.w - cp * v.w);
    float sn = fabsf(dn.x - cn * v.x) + fabsf(dn.y - cn * v.y)
             + fabsf(dn.z - cn * v.z) + fabsf(dn.w - cn * v.w);
    #pragma unroll
    for (int o = 16; o > 0; o >>= 1) {
        sp += __shfl_xor_sync(0xFFFFFFFFu, sp, o);
        sn += __shfl_xor_sync(0xFFFFFFFFu, sn, o);
    }

    if (lane == 0) {
        out[warp]     = sp;
        out[n + warp] = sn;
    }
}

extern "C" void kernel_launch(void* const* d_in, const int* in_sizes, int n_in,
                              void* d_out, int out_size)
{
    const int*    pos_h = (const int*)d_in[0];
    const int*    pos_t = (const int*)d_in[1];
    const int*    pos_r = (const int*)d_in[2];
    const int*    neg_h = (const int*)d_in[3];
    const int*    neg_t = (const int*)d_in[4];
    const int*    neg_r = (const int*)d_in[5];
    const float4* ent   = (const float4*)d_in[6];
    const float4* vvrel = (const float4*)d_in[7];
    const float4* bases = (const float4*)d_in[8];
    float* out = (float*)d_out;

    const int n = in_sizes[0];  // 65536 triples
    const int blocks = (n + WARPS_PER_BLOCK - 1) / WARPS_PER_BLOCK;
    transh_score_kernel<<<blocks, THREADS>>>(
        pos_h, pos_t, pos_r, neg_h, neg_t, neg_r, ent, vvrel, bases, out, n);
}